// round 4
// baseline (speedup 1.0000x reference)
#include <cuda_runtime.h>
#include <math.h>

#define T_STEPS 128
#define BATCH   256
#define OBSD    512
#define ENCD    256
#define HID     512
#define NACT    18
#define NTOT    (T_STEPS * BATCH)   // 32768

#define N_GROUPS 8                   // independent batch groups
#define BLKS_PER_GROUP 16            // h-col tiles per group
#define WS_STRIDE 516
#define AS_STRIDE 36
#define GH_STRIDE 100
#define SCAN_SMEM_FLOATS (96 * WS_STRIDE + 2 * 32 * AS_STRIDE + 32 * GH_STRIDE + 32)
#define SCAN_SMEM_BYTES  (SCAN_SMEM_FLOATS * 4)

// ---------------- scratch (static device globals; no runtime allocation) ----
__device__ float g_h1[(size_t)NTOT * ENCD];
__device__ float g_h2[(size_t)NTOT * ENCD];
__device__ float g_gx[(size_t)NTOT * 3 * HID];
__device__ float g_hidden[(size_t)NTOT * HID];
__device__ float g_state[2][BATCH * HID];
__device__ unsigned g_barriers[N_GROUPS];

// ---------------------------------------------------------------------------
__device__ __forceinline__ unsigned f2tf32(float f) {
    unsigned u;
    asm("cvt.rna.tf32.f32 %0, %1;" : "=r"(u) : "f"(f));
    return u;
}

__device__ __forceinline__ void mma_tf32(float d[4], const unsigned a[4], const unsigned b[2]) {
    asm volatile(
        "mma.sync.aligned.m16n8k8.row.col.f32.tf32.tf32.f32 "
        "{%0,%1,%2,%3}, {%4,%5,%6,%7}, {%8,%9}, {%0,%1,%2,%3};"
        : "+f"(d[0]), "+f"(d[1]), "+f"(d[2]), "+f"(d[3])
        : "r"(a[0]), "r"(a[1]), "r"(a[2]), "r"(a[3]), "r"(b[0]), "r"(b[1]));
}

__device__ __forceinline__ float sigmoidf_(float x) {
    return 1.f / (1.f + expf(-x));
}

__global__ void init_barrier_kernel() {
    if (threadIdx.x < N_GROUPS) g_barriers[threadIdx.x] = 0u;
}

// ---------------------------------------------------------------------------
// Generic C[M,Nc] = act(A[M,K] @ W[Nc,K]^T + bias) using tf32 mma.
// BM=128, BN=64, BK=16, 256 threads (8 warps, 4x2), warptile 32x32.
// ---------------------------------------------------------------------------
template <bool RELU>
__global__ __launch_bounds__(256)
void gemm_tf32_kernel(const float* __restrict__ A,
                      const float* __restrict__ W,
                      const float* __restrict__ bias,
                      float* __restrict__ C,
                      int M, int Nc, int K)
{
    __shared__ float As[128][18];
    __shared__ float Ws[64][18];

    const int tid  = threadIdx.x;
    const int warp = tid >> 5;
    const int lane = tid & 31;
    const int g    = lane >> 2;
    const int tg   = lane & 3;
    const int warp_m = (warp & 3) * 32;
    const int warp_n = (warp >> 2) * 32;
    const int row0 = blockIdx.y * 128;
    const int col0 = blockIdx.x * 64;

    float acc[2][4][4];
#pragma unroll
    for (int i = 0; i < 2; i++)
#pragma unroll
        for (int j = 0; j < 4; j++)
#pragma unroll
            for (int q = 0; q < 4; q++) acc[i][j][q] = 0.f;

    float4 ra[2], rw;
#pragma unroll
    for (int l = 0; l < 2; l++) {
        int i = tid + l * 256;
        ra[l] = *(const float4*)(A + (size_t)(row0 + (i >> 2)) * K + (i & 3) * 4);
    }
    rw = *(const float4*)(W + (size_t)(col0 + (tid >> 2)) * K + (tid & 3) * 4);

    for (int k0 = 0; k0 < K; k0 += 16) {
#pragma unroll
        for (int l = 0; l < 2; l++) {
            int i = tid + l * 256;
            int r = i >> 2, c = (i & 3) * 4;
            As[r][c + 0] = __uint_as_float(f2tf32(ra[l].x));
            As[r][c + 1] = __uint_as_float(f2tf32(ra[l].y));
            As[r][c + 2] = __uint_as_float(f2tf32(ra[l].z));
            As[r][c + 3] = __uint_as_float(f2tf32(ra[l].w));
        }
        {
            int r = tid >> 2, c = (tid & 3) * 4;
            Ws[r][c + 0] = __uint_as_float(f2tf32(rw.x));
            Ws[r][c + 1] = __uint_as_float(f2tf32(rw.y));
            Ws[r][c + 2] = __uint_as_float(f2tf32(rw.z));
            Ws[r][c + 3] = __uint_as_float(f2tf32(rw.w));
        }
        __syncthreads();

        if (k0 + 16 < K) {
#pragma unroll
            for (int l = 0; l < 2; l++) {
                int i = tid + l * 256;
                ra[l] = *(const float4*)(A + (size_t)(row0 + (i >> 2)) * K + k0 + 16 + (i & 3) * 4);
            }
            rw = *(const float4*)(W + (size_t)(col0 + (tid >> 2)) * K + k0 + 16 + (tid & 3) * 4);
        }

#pragma unroll
        for (int ks = 0; ks < 16; ks += 8) {
            unsigned af[2][4], bf[4][2];
#pragma unroll
            for (int mf = 0; mf < 2; mf++) {
                int br = warp_m + mf * 16;
                af[mf][0] = __float_as_uint(As[br + g][ks + tg]);
                af[mf][1] = __float_as_uint(As[br + g + 8][ks + tg]);
                af[mf][2] = __float_as_uint(As[br + g][ks + tg + 4]);
                af[mf][3] = __float_as_uint(As[br + g + 8][ks + tg + 4]);
            }
#pragma unroll
            for (int nf = 0; nf < 4; nf++) {
                int bn = warp_n + nf * 8;
                bf[nf][0] = __float_as_uint(Ws[bn + g][ks + tg]);
                bf[nf][1] = __float_as_uint(Ws[bn + g][ks + tg + 4]);
            }
#pragma unroll
            for (int mf = 0; mf < 2; mf++)
#pragma unroll
                for (int nf = 0; nf < 4; nf++) mma_tf32(acc[mf][nf], af[mf], bf[nf]);
        }
        __syncthreads();
    }

#pragma unroll
    for (int mf = 0; mf < 2; mf++) {
#pragma unroll
        for (int nf = 0; nf < 4; nf++) {
            int r = row0 + warp_m + mf * 16 + g;
            int c = col0 + warp_n + nf * 8 + tg * 2;
            float b0v = bias[c], b1v = bias[c + 1];
            float v0 = acc[mf][nf][0] + b0v;
            float v1 = acc[mf][nf][1] + b1v;
            float v2 = acc[mf][nf][2] + b0v;
            float v3 = acc[mf][nf][3] + b1v;
            if (RELU) {
                v0 = fmaxf(v0, 0.f); v1 = fmaxf(v1, 0.f);
                v2 = fmaxf(v2, 0.f); v3 = fmaxf(v3, 0.f);
            }
            *(float2*)&C[(size_t)r * Nc + c]       = make_float2(v0, v1);
            *(float2*)&C[(size_t)(r + 8) * Nc + c] = make_float2(v2, v3);
        }
    }
}

// ---------------------------------------------------------------------------
// Persistent GRU scan. 128 blocks = 8 batch groups x 16 h-col tiles.
// Groups are fully independent -> per-group barriers (16 blocks each).
// w_hh slice (96 x 512) resident in smem as tf32 for all 128 timesteps.
// ---------------------------------------------------------------------------
__global__ __launch_bounds__(256)
void gru_scan_kernel(const float* __restrict__ gru_st,
                     const float* __restrict__ w_hh,
                     const float* __restrict__ b_hh,
                     const float* __restrict__ done)
{
    extern __shared__ float sm[];
    float* Ws     = sm;                                  // [96][WS_STRIDE]
    float* Asm    = Ws + 96 * WS_STRIDE;                 // [2][32][AS_STRIDE]
    float* ghs    = Asm + 2 * 32 * AS_STRIDE;            // [32][GH_STRIDE]
    float* s_mask = ghs + 32 * GH_STRIDE;                // [32]

    const int tid  = threadIdx.x;
    const int warp = tid >> 5;
    const int lane = tid & 31;
    const int g    = lane >> 2;
    const int tg   = lane & 3;
    const int bid  = blockIdx.x;
    const int col0 = (bid & 15) * 32;     // h-col block
    const int gid  = bid >> 4;            // batch group
    const int row0 = gid * 32;
    const int warp_m = (warp & 1) * 16;
    const int warp_n = (warp >> 1) * 24;

    // ---- preload w_hh slice (96 rows x 512 K) as tf32 ----
    for (int i = tid; i < 96 * 128; i += 256) {
        int r  = i >> 7;
        int c4 = (i & 127) * 4;
        int gg = r >> 5, lr = r & 31;
        float4 v = *(const float4*)(w_hh + (size_t)(gg * HID + col0 + lr) * HID + c4);
        float* d = Ws + r * WS_STRIDE + c4;
        d[0] = __uint_as_float(f2tf32(v.x));
        d[1] = __uint_as_float(f2tf32(v.y));
        d[2] = __uint_as_float(f2tf32(v.z));
        d[3] = __uint_as_float(f2tf32(v.w));
    }

    // thread mapping shared by A-staging and gate math
    const int r_a  = tid >> 3;           // 0..31 (batch row within tile)
    const int c4a  = (tid & 7) * 4;      // 4-col offset

    // b_hh registers (constant across all steps)
    float brf[4], bzf[4], bnf[4];
    {
        float4 br_ = *(const float4*)(b_hh + col0 + c4a);
        float4 bz_ = *(const float4*)(b_hh + HID + col0 + c4a);
        float4 bn_ = *(const float4*)(b_hh + 2 * HID + col0 + c4a);
        brf[0]=br_.x; brf[1]=br_.y; brf[2]=br_.z; brf[3]=br_.w;
        bzf[0]=bz_.x; bzf[1]=bz_.y; bzf[2]=bz_.z; bzf[3]=bz_.w;
        bnf[0]=bn_.x; bnf[1]=bn_.y; bnf[2]=bn_.z; bnf[3]=bn_.w;
    }
    __syncthreads();

    float* sb0 = g_state[0];
    float* sb1 = g_state[1];
    const int bg = row0 + r_a;           // global batch row for this thread

    for (int t = 0; t < T_STEPS; t++) {
        const float* sin = (t == 0) ? gru_st : ((t & 1) ? sb1 : sb0);
        float*       sout = (t & 1) ? sb0 : sb1;

        if (tid < 32) s_mask[tid] = 1.0f - __ldg(done + t * BATCH + row0 + tid);

        // early loads (independent of gh) — hide latency under the mma loop
        const float* gxr = g_gx + ((size_t)t * BATCH + bg) * (3 * HID);
        float4 xr  = *(const float4*)(gxr + col0 + c4a);
        float4 xz  = *(const float4*)(gxr + HID + col0 + c4a);
        float4 xn  = *(const float4*)(gxr + 2 * HID + col0 + c4a);
        float4 hp4 = __ldcg((const float4*)(sin + (size_t)bg * HID + col0 + c4a));

        const float* arow = sin + (size_t)bg * HID;
        float4 ra = __ldcg((const float4*)(arow + c4a));
        __syncthreads();

        float acc[3][4];
#pragma unroll
        for (int nf = 0; nf < 3; nf++)
#pragma unroll
            for (int q = 0; q < 4; q++) acc[nf][q] = 0.f;

        const float m_a = s_mask[r_a];

#pragma unroll 4
        for (int kk = 0; kk < 16; kk++) {
            float* Ab = Asm + (kk & 1) * (32 * AS_STRIDE);
            float* d  = Ab + r_a * AS_STRIDE + c4a;
            d[0] = __uint_as_float(f2tf32(ra.x * m_a));
            d[1] = __uint_as_float(f2tf32(ra.y * m_a));
            d[2] = __uint_as_float(f2tf32(ra.z * m_a));
            d[3] = __uint_as_float(f2tf32(ra.w * m_a));
            if (kk < 15)
                ra = __ldcg((const float4*)(arow + (kk + 1) * 32 + c4a));
            __syncthreads();

            const float* Am0 = Ab + (warp_m + g) * AS_STRIDE;
            const float* Am1 = Ab + (warp_m + g + 8) * AS_STRIDE;
#pragma unroll
            for (int ks = 0; ks < 32; ks += 8) {
                unsigned af[4];
                af[0] = __float_as_uint(Am0[ks + tg]);
                af[1] = __float_as_uint(Am1[ks + tg]);
                af[2] = __float_as_uint(Am0[ks + tg + 4]);
                af[3] = __float_as_uint(Am1[ks + tg + 4]);
#pragma unroll
                for (int nf = 0; nf < 3; nf++) {
                    const float* Wr = Ws + (size_t)(warp_n + nf * 8 + g) * WS_STRIDE + kk * 32 + ks + tg;
                    unsigned bf[2];
                    bf[0] = __float_as_uint(Wr[0]);
                    bf[1] = __float_as_uint(Wr[4]);
                    mma_tf32(acc[nf], af, bf);
                }
            }
        }

        // stage gh into smem (combined cols: 0..31 r, 32..63 z, 64..95 n)
#pragma unroll
        for (int nf = 0; nf < 3; nf++) {
            int c = warp_n + nf * 8 + tg * 2;
            int r = warp_m + g;
            ghs[r * GH_STRIDE + c]           = acc[nf][0];
            ghs[r * GH_STRIDE + c + 1]       = acc[nf][1];
            ghs[(r + 8) * GH_STRIDE + c]     = acc[nf][2];
            ghs[(r + 8) * GH_STRIDE + c + 1] = acc[nf][3];
        }
        __syncthreads();

        // fused gate math: thread -> batch row r_a, 4 h-cols at c4a
        {
            const float m = s_mask[r_a];
            float xrf[4] = {xr.x, xr.y, xr.z, xr.w};
            float xzf[4] = {xz.x, xz.y, xz.z, xz.w};
            float xnf[4] = {xn.x, xn.y, xn.z, xn.w};
            float hpf[4] = {hp4.x, hp4.y, hp4.z, hp4.w};
            float hnew[4];
#pragma unroll
            for (int j = 0; j < 4; j++) {
                float ghr = ghs[r_a * GH_STRIDE + c4a + j] + brf[j];
                float ghz = ghs[r_a * GH_STRIDE + 32 + c4a + j] + bzf[j];
                float ghn = ghs[r_a * GH_STRIDE + 64 + c4a + j] + bnf[j];
                float r = sigmoidf_(xrf[j] + ghr);
                float z = sigmoidf_(xzf[j] + ghz);
                float n = tanhf(xnf[j] + r * ghn);
                hnew[j] = (1.f - z) * n + z * (hpf[j] * m);
            }
            float4 o = make_float4(hnew[0], hnew[1], hnew[2], hnew[3]);
            *(float4*)(sout + (size_t)bg * HID + col0 + c4a) = o;
            *(float4*)(g_hidden + ((size_t)t * BATCH + bg) * HID + col0 + c4a) = o;
        }

        // ---- per-group barrier (skip after last step) ----
        if (t < T_STEPS - 1) {
            __threadfence();
            __syncthreads();
            if (tid == 0) {
                atomicAdd(&g_barriers[gid], 1u);
                unsigned target = (unsigned)BLKS_PER_GROUP * (unsigned)(t + 1);
                while (*(volatile unsigned*)&g_barriers[gid] < target) { }
                __threadfence();
            }
            __syncthreads();
        }
    }
}

// ---------------------------------------------------------------------------
// Heads: one warp per row n.
// ---------------------------------------------------------------------------
__global__ __launch_bounds__(256)
void heads_kernel(const int* __restrict__ action,
                  const float* __restrict__ w_actor,
                  const float* __restrict__ b_actor,
                  const float* __restrict__ w_critic,
                  const float* __restrict__ b_critic,
                  float* __restrict__ out)
{
    __shared__ float s_wa[NACT * HID];
    __shared__ float s_wc[HID];
    __shared__ float s_ba[NACT];

    const int tid = threadIdx.x;
    for (int i = tid; i < NACT * HID; i += 256) s_wa[i] = w_actor[i];
    for (int i = tid; i < HID; i += 256) s_wc[i] = w_critic[i];
    if (tid < NACT) s_ba[tid] = b_actor[tid];
    __syncthreads();

    const int warp = tid >> 5;
    const int lane = tid & 31;
    const int n = blockIdx.x * 8 + warp;

    const float* hrow = g_hidden + (size_t)n * HID;
    float h[16];
#pragma unroll
    for (int i = 0; i < 16; i++) h[i] = hrow[lane + 32 * i];

    float l[NACT];
#pragma unroll
    for (int a = 0; a < NACT; a++) {
        float p = 0.f;
        const float* wa = s_wa + a * HID;
#pragma unroll
        for (int i = 0; i < 16; i++) p += h[i] * wa[lane + 32 * i];
#pragma unroll
        for (int o = 16; o > 0; o >>= 1) p += __shfl_xor_sync(0xffffffffu, p, o);
        l[a] = p + s_ba[a];
    }

    float v = 0.f;
#pragma unroll
    for (int i = 0; i < 16; i++) v += h[i] * s_wc[lane + 32 * i];
#pragma unroll
    for (int o = 16; o > 0; o >>= 1) v += __shfl_xor_sync(0xffffffffu, v, o);
    v += b_critic[0];

    float mx = l[0];
#pragma unroll
    for (int a = 1; a < NACT; a++) mx = fmaxf(mx, l[a]);
    float s = 0.f;
#pragma unroll
    for (int a = 0; a < NACT; a++) s += expf(l[a] - mx);
    float lse = mx + logf(s);

    float ent = 0.f;
#pragma unroll
    for (int a = 0; a < NACT; a++) ent += expf(l[a] - lse) * (lse - l[a]);

    int act = action[n];
    float lp = 0.f;
#pragma unroll
    for (int a = 0; a < NACT; a++) lp += (a == act) ? (l[a] - lse) : 0.f;

    if (lane == 0) {
        out[n] = lp;
        out[NTOT + n] = ent;
        out[2 * NTOT + n] = v;
    }
}

__global__ void copy_state_kernel(const float* __restrict__ src, float* __restrict__ dst)
{
    int i = blockIdx.x * 256 + threadIdx.x;
    dst[i] = src[i];
}

// ---------------------------------------------------------------------------
extern "C" void kernel_launch(void* const* d_in, const int* in_sizes, int n_in,
                              void* d_out, int out_size)
{
    const float* x        = (const float*)d_in[0];
    const float* gru_st   = (const float*)d_in[1];
    const float* done     = (const float*)d_in[2];
    const int*   action   = (const int*)  d_in[3];
    const float* w1       = (const float*)d_in[4];
    const float* b1       = (const float*)d_in[5];
    const float* w2       = (const float*)d_in[6];
    const float* b2       = (const float*)d_in[7];
    const float* w_ih     = (const float*)d_in[8];
    const float* w_hh     = (const float*)d_in[9];
    const float* b_ih     = (const float*)d_in[10];
    const float* b_hh     = (const float*)d_in[11];
    const float* w_actor  = (const float*)d_in[12];
    const float* b_actor  = (const float*)d_in[13];
    const float* w_critic = (const float*)d_in[14];
    const float* b_critic = (const float*)d_in[15];
    float* out = (float*)d_out;

    float *h1, *h2, *gx, *st;
    cudaGetSymbolAddress((void**)&h1, g_h1);
    cudaGetSymbolAddress((void**)&h2, g_h2);
    cudaGetSymbolAddress((void**)&gx, g_gx);
    cudaGetSymbolAddress((void**)&st, g_state);
    float* s0 = st;

    static int smem_set = 0;
    if (!smem_set) {
        cudaFuncSetAttribute(gru_scan_kernel,
                             cudaFuncAttributeMaxDynamicSharedMemorySize,
                             SCAN_SMEM_BYTES);
        smem_set = 1;
    }

    // encoder layer 1: (N,512)@(512,256)^T -> h1
    gemm_tf32_kernel<true><<<dim3(ENCD / 64, NTOT / 128), 256>>>(
        x, w1, b1, h1, NTOT, ENCD, OBSD);
    // encoder layer 2: (N,256)@(256,256)^T -> h2
    gemm_tf32_kernel<true><<<dim3(ENCD / 64, NTOT / 128), 256>>>(
        h1, w2, b2, h2, NTOT, ENCD, ENCD);
    // input-side gates: (N,256)@(256,1536)^T -> gx
    gemm_tf32_kernel<false><<<dim3(3 * HID / 64, NTOT / 128), 256>>>(
        h2, w_ih, b_ih, gx, NTOT, 3 * HID, ENCD);

    // persistent GRU scan
    init_barrier_kernel<<<1, 32>>>();
    gru_scan_kernel<<<N_GROUPS * BLKS_PER_GROUP, 256, SCAN_SMEM_BYTES>>>(
        gru_st, w_hh, b_hh, done);

    // final state (t=127 wrote g_state[0])
    copy_state_kernel<<<BATCH * HID / 256, 256>>>(s0, out + 3 * NTOT);

    heads_kernel<<<NTOT / 8, 256>>>(action, w_actor, b_actor, w_critic, b_critic, out);
}

// round 5
// speedup vs baseline: 1.0692x; 1.0692x over previous
#include <cuda_runtime.h>
#include <math.h>

#define T_STEPS 128
#define BATCH   256
#define OBSD    512
#define ENCD    256
#define HID     512
#define NACT    18
#define NTOT    (T_STEPS * BATCH)   // 32768

#define N_GROUPS 8
#define BLKS_PER_GROUP 16
#define AS_STRIDE 68
// smem floats: B frag 12*64*32*2 = 49152, A double buffer 2*32*68 = 4352
#define BFRAG_FLOATS (12 * 64 * 32 * 2)
#define SCAN_SMEM_FLOATS (BFRAG_FLOATS + 2 * 32 * AS_STRIDE)
#define SCAN_SMEM_BYTES  (SCAN_SMEM_FLOATS * 4)

// ---------------- scratch (static device globals; no runtime allocation) ----
__device__ float g_h1[(size_t)NTOT * ENCD];
__device__ float g_h2[(size_t)NTOT * ENCD];
__device__ float g_gx[(size_t)NTOT * 3 * HID];
__device__ float g_hidden[(size_t)NTOT * HID];
__device__ float g_state[2][BATCH * HID];
__device__ float g_bcomb[3 * HID];
__device__ unsigned g_barriers[N_GROUPS][32];   // 128B-padded per-group counters

// ---------------------------------------------------------------------------
__device__ __forceinline__ unsigned f2tf32(float f) {
    unsigned u;
    asm("cvt.rna.tf32.f32 %0, %1;" : "=r"(u) : "f"(f));
    return u;
}

__device__ __forceinline__ void mma_tf32(float d[4], const unsigned a[4], const unsigned b[2]) {
    asm volatile(
        "mma.sync.aligned.m16n8k8.row.col.f32.tf32.tf32.f32 "
        "{%0,%1,%2,%3}, {%4,%5,%6,%7}, {%8,%9}, {%0,%1,%2,%3};"
        : "+f"(d[0]), "+f"(d[1]), "+f"(d[2]), "+f"(d[3])
        : "r"(a[0]), "r"(a[1]), "r"(a[2]), "r"(a[3]), "r"(b[0]), "r"(b[1]));
}

__device__ __forceinline__ float sigmoidf_(float x) {
    return 1.f / (1.f + expf(-x));
}

__global__ void init_barrier_kernel(const float* __restrict__ b_ih,
                                    const float* __restrict__ b_hh)
{
    int i = blockIdx.x * 256 + threadIdx.x;
    if (i < N_GROUPS) g_barriers[i][0] = 0u;
    // combined bias: b_ih + b_hh for r,z gates; b_ih only for n gate
    if (i < 3 * HID)
        g_bcomb[i] = b_ih[i] + ((i < 2 * HID) ? b_hh[i] : 0.f);
}

// ---------------------------------------------------------------------------
// Generic C[M,Nc] = act(A[M,K] @ W[Nc,K]^T + bias) using tf32 mma.
// BM=128, BN=64, BK=16, 256 threads (8 warps, 4x2), warptile 32x32.
// ---------------------------------------------------------------------------
template <bool RELU>
__global__ __launch_bounds__(256)
void gemm_tf32_kernel(const float* __restrict__ A,
                      const float* __restrict__ W,
                      const float* __restrict__ bias,
                      float* __restrict__ C,
                      int M, int Nc, int K)
{
    __shared__ float As[128][18];
    __shared__ float Ws[64][18];

    const int tid  = threadIdx.x;
    const int warp = tid >> 5;
    const int lane = tid & 31;
    const int g    = lane >> 2;
    const int tg   = lane & 3;
    const int warp_m = (warp & 3) * 32;
    const int warp_n = (warp >> 2) * 32;
    const int row0 = blockIdx.y * 128;
    const int col0 = blockIdx.x * 64;

    float acc[2][4][4];
#pragma unroll
    for (int i = 0; i < 2; i++)
#pragma unroll
        for (int j = 0; j < 4; j++)
#pragma unroll
            for (int q = 0; q < 4; q++) acc[i][j][q] = 0.f;

    float4 ra[2], rw;
#pragma unroll
    for (int l = 0; l < 2; l++) {
        int i = tid + l * 256;
        ra[l] = *(const float4*)(A + (size_t)(row0 + (i >> 2)) * K + (i & 3) * 4);
    }
    rw = *(const float4*)(W + (size_t)(col0 + (tid >> 2)) * K + (tid & 3) * 4);

    for (int k0 = 0; k0 < K; k0 += 16) {
#pragma unroll
        for (int l = 0; l < 2; l++) {
            int i = tid + l * 256;
            int r = i >> 2, c = (i & 3) * 4;
            As[r][c + 0] = __uint_as_float(f2tf32(ra[l].x));
            As[r][c + 1] = __uint_as_float(f2tf32(ra[l].y));
            As[r][c + 2] = __uint_as_float(f2tf32(ra[l].z));
            As[r][c + 3] = __uint_as_float(f2tf32(ra[l].w));
        }
        {
            int r = tid >> 2, c = (tid & 3) * 4;
            Ws[r][c + 0] = __uint_as_float(f2tf32(rw.x));
            Ws[r][c + 1] = __uint_as_float(f2tf32(rw.y));
            Ws[r][c + 2] = __uint_as_float(f2tf32(rw.z));
            Ws[r][c + 3] = __uint_as_float(f2tf32(rw.w));
        }
        __syncthreads();

        if (k0 + 16 < K) {
#pragma unroll
            for (int l = 0; l < 2; l++) {
                int i = tid + l * 256;
                ra[l] = *(const float4*)(A + (size_t)(row0 + (i >> 2)) * K + k0 + 16 + (i & 3) * 4);
            }
            rw = *(const float4*)(W + (size_t)(col0 + (tid >> 2)) * K + k0 + 16 + (tid & 3) * 4);
        }

#pragma unroll
        for (int ks = 0; ks < 16; ks += 8) {
            unsigned af[2][4], bf[4][2];
#pragma unroll
            for (int mf = 0; mf < 2; mf++) {
                int br = warp_m + mf * 16;
                af[mf][0] = __float_as_uint(As[br + g][ks + tg]);
                af[mf][1] = __float_as_uint(As[br + g + 8][ks + tg]);
                af[mf][2] = __float_as_uint(As[br + g][ks + tg + 4]);
                af[mf][3] = __float_as_uint(As[br + g + 8][ks + tg + 4]);
            }
#pragma unroll
            for (int nf = 0; nf < 4; nf++) {
                int bn = warp_n + nf * 8;
                bf[nf][0] = __float_as_uint(Ws[bn + g][ks + tg]);
                bf[nf][1] = __float_as_uint(Ws[bn + g][ks + tg + 4]);
            }
#pragma unroll
            for (int mf = 0; mf < 2; mf++)
#pragma unroll
                for (int nf = 0; nf < 4; nf++) mma_tf32(acc[mf][nf], af[mf], bf[nf]);
        }
        __syncthreads();
    }

#pragma unroll
    for (int mf = 0; mf < 2; mf++) {
#pragma unroll
        for (int nf = 0; nf < 4; nf++) {
            int r = row0 + warp_m + mf * 16 + g;
            int c = col0 + warp_n + nf * 8 + tg * 2;
            float b0v = bias[c], b1v = bias[c + 1];
            float v0 = acc[mf][nf][0] + b0v;
            float v1 = acc[mf][nf][1] + b1v;
            float v2 = acc[mf][nf][2] + b0v;
            float v3 = acc[mf][nf][3] + b1v;
            if (RELU) {
                v0 = fmaxf(v0, 0.f); v1 = fmaxf(v1, 0.f);
                v2 = fmaxf(v2, 0.f); v3 = fmaxf(v3, 0.f);
            }
            *(float2*)&C[(size_t)r * Nc + c]       = make_float2(v0, v1);
            *(float2*)&C[(size_t)(r + 8) * Nc + c] = make_float2(v2, v3);
        }
    }
}

// ---------------------------------------------------------------------------
// Persistent GRU scan. 128 blocks = 8 batch groups x 16 h-col tiles.
// Per-group padded barriers. w_hh slice (96 x 512) resident in smem in
// mma-fragment layout. Warps own all 3 gates for their 8 h-cols -> gate math
// entirely in registers (no smem staging of gh).
// ---------------------------------------------------------------------------
__global__ __launch_bounds__(256)
void gru_scan_kernel(const float* __restrict__ gru_st,
                     const float* __restrict__ w_hh,
                     const float* __restrict__ b_hh,
                     const float* __restrict__ done)
{
    extern __shared__ float sm[];
    float* Bf  = sm;                    // fragment-layout B: [nt(12)][k8(64)][lane(32)][2]
    float* Asm = sm + BFRAG_FLOATS;     // [2][32][AS_STRIDE]

    const int tid  = threadIdx.x;
    const int warp = tid >> 5;
    const int lane = tid & 31;
    const int g    = lane >> 2;
    const int tg   = lane & 3;
    const int bid  = blockIdx.x;
    const int col0 = (bid & 15) * 32;     // h-col block
    const int gid  = bid >> 4;            // batch group
    const int row0 = gid * 32;
    const int warp_m  = (warp & 1) * 16;  // 16 batch rows
    const int warp_hn = (warp >> 1) * 8;  // 8 h-cols, all 3 gates

    // ---- preload w_hh slice (96 combined rows x 512 K) into fragment layout
    for (int i = tid; i < 96 * 64; i += 256) {
        int cr = i >> 6;                 // combined row 0..95
        int k8 = i & 63;                 // k-octet 0..63
        int gate = cr >> 5, lc = cr & 31;
        const float* wrow = w_hh + (size_t)(gate * HID + col0 + lc) * HID + k8 * 8;
        float4 w0 = *(const float4*)(wrow);
        float4 w1 = *(const float4*)(wrow + 4);
        int nt = cr >> 3, gg = cr & 7;
        float* dst = Bf + (size_t)((nt * 64 + k8) * 32 + gg * 4) * 2;
        // lane slot tg holds pair (k8*8+tg, k8*8+tg+4)
        float4 o0 = make_float4(__uint_as_float(f2tf32(w0.x)), __uint_as_float(f2tf32(w1.x)),
                                __uint_as_float(f2tf32(w0.y)), __uint_as_float(f2tf32(w1.y)));
        float4 o1 = make_float4(__uint_as_float(f2tf32(w0.z)), __uint_as_float(f2tf32(w1.z)),
                                __uint_as_float(f2tf32(w0.w)), __uint_as_float(f2tf32(w1.w)));
        *(float4*)(dst)     = o0;
        *(float4*)(dst + 4) = o1;
    }

    // n-gate hidden bias for this thread's 2 cols (constant over t, rows)
    const int ccol = col0 + warp_hn + tg * 2;
    const float2 bn2 = *(const float2*)(b_hh + 2 * HID + ccol);
    const int nt_base = warp_hn >> 3;    // 0..3

    const int r_a  = tid >> 3;           // staging: batch row 0..31
    const int c4a  = (tid & 7) * 4;      // staging: k offset within 32
    const int rr0  = warp_m + g;         // gate-math rows
    const int rr1  = rr0 + 8;

    __syncthreads();

    float* sb0 = g_state[0];
    float* sb1 = g_state[1];

    for (int t = 0; t < T_STEPS; t++) {
        const float* sin = (t == 0) ? gru_st : ((t & 1) ? sb1 : sb0);
        float*       sout = (t & 1) ? sb0 : sb1;

        // staging mask (direct LDG, no smem)
        const float m_a = 1.0f - __ldg(done + t * BATCH + row0 + r_a);
        const float* arow = sin + (size_t)(row0 + r_a) * HID;
        float4 ra0 = __ldcg((const float4*)(arow + c4a));
        float4 ra1 = __ldcg((const float4*)(arow + 32 + c4a));

        // prefetch gx / h_prev for gate math (hidden under mma loop)
        const float* gx0 = g_gx + ((size_t)(t * BATCH + row0 + rr0)) * (3 * HID);
        const float* gx1 = g_gx + ((size_t)(t * BATCH + row0 + rr1)) * (3 * HID);
        float2 xr0 = *(const float2*)(gx0 + ccol);
        float2 xz0 = *(const float2*)(gx0 + HID + ccol);
        float2 xn0 = *(const float2*)(gx0 + 2 * HID + ccol);
        float2 xr1 = *(const float2*)(gx1 + ccol);
        float2 xz1 = *(const float2*)(gx1 + HID + ccol);
        float2 xn1 = *(const float2*)(gx1 + 2 * HID + ccol);
        float2 hp0 = __ldcg((const float2*)(sin + (size_t)(row0 + rr0) * HID + ccol));
        float2 hp1 = __ldcg((const float2*)(sin + (size_t)(row0 + rr1) * HID + ccol));
        const float m0 = 1.0f - __ldg(done + t * BATCH + row0 + rr0);
        const float m1 = 1.0f - __ldg(done + t * BATCH + row0 + rr1);

        float acc[3][4];
#pragma unroll
        for (int gt = 0; gt < 3; gt++)
#pragma unroll
            for (int q = 0; q < 4; q++) acc[gt][q] = 0.f;

        // ---- K loop: 8 phases of 64 ----
#pragma unroll 2
        for (int p = 0; p < 8; p++) {
            float* Ab = Asm + (p & 1) * (32 * AS_STRIDE);
            {
                float* d = Ab + r_a * AS_STRIDE + c4a;
                d[0] = __uint_as_float(f2tf32(ra0.x * m_a));
                d[1] = __uint_as_float(f2tf32(ra0.y * m_a));
                d[2] = __uint_as_float(f2tf32(ra0.z * m_a));
                d[3] = __uint_as_float(f2tf32(ra0.w * m_a));
                float* d2 = d + 32;
                d2[0] = __uint_as_float(f2tf32(ra1.x * m_a));
                d2[1] = __uint_as_float(f2tf32(ra1.y * m_a));
                d2[2] = __uint_as_float(f2tf32(ra1.z * m_a));
                d2[3] = __uint_as_float(f2tf32(ra1.w * m_a));
            }
            if (p < 7) {
                ra0 = __ldcg((const float4*)(arow + (p + 1) * 64 + c4a));
                ra1 = __ldcg((const float4*)(arow + (p + 1) * 64 + 32 + c4a));
            }
            __syncthreads();

            const float* Am0 = Ab + (warp_m + g) * AS_STRIDE;
            const float* Am1 = Ab + (warp_m + g + 8) * AS_STRIDE;
#pragma unroll
            for (int ks = 0; ks < 64; ks += 8) {
                unsigned af[4];
                af[0] = __float_as_uint(Am0[ks + tg]);
                af[1] = __float_as_uint(Am1[ks + tg]);
                af[2] = __float_as_uint(Am0[ks + tg + 4]);
                af[3] = __float_as_uint(Am1[ks + tg + 4]);
                int k8 = p * 8 + (ks >> 3);
#pragma unroll
                for (int gt = 0; gt < 3; gt++) {
                    int nt = gt * 4 + nt_base;
                    float2 b2 = *(const float2*)(Bf + (size_t)((nt * 64 + k8) * 32 + lane) * 2);
                    unsigned bf[2] = { __float_as_uint(b2.x), __float_as_uint(b2.y) };
                    mma_tf32(acc[gt], af, bf);
                }
            }
        }

        // ---- fused gate math in registers (b_ih + b_hh[r,z] pre-folded in gx)
        {
            float hn0x, hn0y, hn1x, hn1y;
            {
                float r = sigmoidf_(xr0.x + acc[0][0]);
                float z = sigmoidf_(xz0.x + acc[1][0]);
                float n = tanhf(xn0.x + r * (acc[2][0] + bn2.x));
                hn0x = (1.f - z) * n + z * (hp0.x * m0);
                r = sigmoidf_(xr0.y + acc[0][1]);
                z = sigmoidf_(xz0.y + acc[1][1]);
                n = tanhf(xn0.y + r * (acc[2][1] + bn2.y));
                hn0y = (1.f - z) * n + z * (hp0.y * m0);
                r = sigmoidf_(xr1.x + acc[0][2]);
                z = sigmoidf_(xz1.x + acc[1][2]);
                n = tanhf(xn1.x + r * (acc[2][2] + bn2.x));
                hn1x = (1.f - z) * n + z * (hp1.x * m1);
                r = sigmoidf_(xr1.y + acc[0][3]);
                z = sigmoidf_(xz1.y + acc[1][3]);
                n = tanhf(xn1.y + r * (acc[2][3] + bn2.y));
                hn1y = (1.f - z) * n + z * (hp1.y * m1);
            }
            float2 o0 = make_float2(hn0x, hn0y);
            float2 o1 = make_float2(hn1x, hn1y);
            *(float2*)(sout + (size_t)(row0 + rr0) * HID + ccol) = o0;
            *(float2*)(sout + (size_t)(row0 + rr1) * HID + ccol) = o1;
            *(float2*)(g_hidden + ((size_t)(t * BATCH + row0 + rr0)) * HID + ccol) = o0;
            *(float2*)(g_hidden + ((size_t)(t * BATCH + row0 + rr1)) * HID + ccol) = o1;
        }

        // ---- per-group barrier (padded counters; skip after last step) ----
        if (t < T_STEPS - 1) {
            __threadfence();
            __syncthreads();
            if (tid == 0) {
                atomicAdd(&g_barriers[gid][0], 1u);
                unsigned target = (unsigned)BLKS_PER_GROUP * (unsigned)(t + 1);
                while (*(volatile unsigned*)&g_barriers[gid][0] < target) { }
                __threadfence();
            }
            __syncthreads();
        }
    }
}

// ---------------------------------------------------------------------------
// Heads: one warp per row n.
// ---------------------------------------------------------------------------
__global__ __launch_bounds__(256)
void heads_kernel(const int* __restrict__ action,
                  const float* __restrict__ w_actor,
                  const float* __restrict__ b_actor,
                  const float* __restrict__ w_critic,
                  const float* __restrict__ b_critic,
                  float* __restrict__ out)
{
    __shared__ float s_wa[NACT * HID];
    __shared__ float s_wc[HID];
    __shared__ float s_ba[NACT];

    const int tid = threadIdx.x;
    for (int i = tid; i < NACT * HID; i += 256) s_wa[i] = w_actor[i];
    for (int i = tid; i < HID; i += 256) s_wc[i] = w_critic[i];
    if (tid < NACT) s_ba[tid] = b_actor[tid];
    __syncthreads();

    const int warp = tid >> 5;
    const int lane = tid & 31;
    const int n = blockIdx.x * 8 + warp;

    const float* hrow = g_hidden + (size_t)n * HID;
    float h[16];
#pragma unroll
    for (int i = 0; i < 16; i++) h[i] = hrow[lane + 32 * i];

    float l[NACT];
#pragma unroll
    for (int a = 0; a < NACT; a++) {
        float p = 0.f;
        const float* wa = s_wa + a * HID;
#pragma unroll
        for (int i = 0; i < 16; i++) p += h[i] * wa[lane + 32 * i];
#pragma unroll
        for (int o = 16; o > 0; o >>= 1) p += __shfl_xor_sync(0xffffffffu, p, o);
        l[a] = p + s_ba[a];
    }

    float v = 0.f;
#pragma unroll
    for (int i = 0; i < 16; i++) v += h[i] * s_wc[lane + 32 * i];
#pragma unroll
    for (int o = 16; o > 0; o >>= 1) v += __shfl_xor_sync(0xffffffffu, v, o);
    v += b_critic[0];

    float mx = l[0];
#pragma unroll
    for (int a = 1; a < NACT; a++) mx = fmaxf(mx, l[a]);
    float s = 0.f;
#pragma unroll
    for (int a = 0; a < NACT; a++) s += expf(l[a] - mx);
    float lse = mx + logf(s);

    float ent = 0.f;
#pragma unroll
    for (int a = 0; a < NACT; a++) ent += expf(l[a] - lse) * (lse - l[a]);

    int act = action[n];
    float lp = 0.f;
#pragma unroll
    for (int a = 0; a < NACT; a++) lp += (a == act) ? (l[a] - lse) : 0.f;

    if (lane == 0) {
        out[n] = lp;
        out[NTOT + n] = ent;
        out[2 * NTOT + n] = v;
    }
}

__global__ void copy_state_kernel(const float* __restrict__ src, float* __restrict__ dst)
{
    int i = blockIdx.x * 256 + threadIdx.x;
    dst[i] = src[i];
}

// ---------------------------------------------------------------------------
extern "C" void kernel_launch(void* const* d_in, const int* in_sizes, int n_in,
                              void* d_out, int out_size)
{
    const float* x        = (const float*)d_in[0];
    const float* gru_st   = (const float*)d_in[1];
    const float* done     = (const float*)d_in[2];
    const int*   action   = (const int*)  d_in[3];
    const float* w1       = (const float*)d_in[4];
    const float* b1       = (const float*)d_in[5];
    const float* w2       = (const float*)d_in[6];
    const float* b2       = (const float*)d_in[7];
    const float* w_ih     = (const float*)d_in[8];
    const float* w_hh     = (const float*)d_in[9];
    const float* b_ih     = (const float*)d_in[10];
    const float* b_hh     = (const float*)d_in[11];
    const float* w_actor  = (const float*)d_in[12];
    const float* b_actor  = (const float*)d_in[13];
    const float* w_critic = (const float*)d_in[14];
    const float* b_critic = (const float*)d_in[15];
    float* out = (float*)d_out;

    float *h1, *h2, *gx, *st, *bc;
    cudaGetSymbolAddress((void**)&h1, g_h1);
    cudaGetSymbolAddress((void**)&h2, g_h2);
    cudaGetSymbolAddress((void**)&gx, g_gx);
    cudaGetSymbolAddress((void**)&st, g_state);
    cudaGetSymbolAddress((void**)&bc, g_bcomb);
    float* s0 = st;

    static int smem_set = 0;
    if (!smem_set) {
        cudaFuncSetAttribute(gru_scan_kernel,
                             cudaFuncAttributeMaxDynamicSharedMemorySize,
                             SCAN_SMEM_BYTES);
        smem_set = 1;
    }

    // barriers + combined bias (b_ih + b_hh for r,z gates)
    init_barrier_kernel<<<(3 * HID + 255) / 256, 256>>>(b_ih, b_hh);

    // encoder layer 1: (N,512)@(512,256)^T -> h1
    gemm_tf32_kernel<true><<<dim3(ENCD / 64, NTOT / 128), 256>>>(
        x, w1, b1, h1, NTOT, ENCD, OBSD);
    // encoder layer 2: (N,256)@(256,256)^T -> h2
    gemm_tf32_kernel<true><<<dim3(ENCD / 64, NTOT / 128), 256>>>(
        h1, w2, b2, h2, NTOT, ENCD, ENCD);
    // input-side gates (bias = b_ih + b_hh[r,z]): (N,256)@(256,1536)^T -> gx
    gemm_tf32_kernel<false><<<dim3(3 * HID / 64, NTOT / 128), 256>>>(
        h2, w_ih, bc, gx, NTOT, 3 * HID, ENCD);

    // persistent GRU scan
    gru_scan_kernel<<<N_GROUPS * BLKS_PER_GROUP, 256, SCAN_SMEM_BYTES>>>(
        gru_st, w_hh, b_hh, done);

    // final state (t=127 wrote g_state[0])
    copy_state_kernel<<<BATCH * HID / 256, 256>>>(s0, out + 3 * NTOT);

    heads_kernel<<<NTOT / 8, 256>>>(action, w_actor, b_actor, w_critic, b_critic, out);
}